// round 9
// baseline (speedup 1.0000x reference)
#include <cuda_runtime.h>
#include <math.h>

#define NMAX 4096
#define FMAX 1024
#define IMGF 256.0f
#define INV_SIGMA (1.0f / 3e-05f)

#define TILES 32            // 32x32 tiles of 8x8 pixels
#define NBLK  (TILES * TILES)
#define TPB   64            // threads per raster block (one per pixel of 8x8 tile)

// Scratch (no allocations allowed in kernel_launch)
__device__ float4 g_f0[FMAX];   // A0,B0,C0,A1
__device__ float4 g_f1[FMAX];   // B1,C1,A2,B2
__device__ float  g_f2[FMAX];   // C2
__device__ float  g_partial[NBLK];
__device__ unsigned g_ticket = 0;

// ---------------- Kernel 1: project vertices + face edge coefficients ----------------
__global__ void __launch_bounds__(1024) prep_kernel(const float* __restrict__ verts,
                                                    const float* __restrict__ K,
                                                    const float* __restrict__ R,
                                                    const float* __restrict__ t,
                                                    const int* __restrict__ faces,
                                                    int N, int F) {
    __shared__ float2 v2d[NMAX];

    float R0 = R[0], R1 = R[1], R2 = R[2];
    float R3 = R[3], R4 = R[4], R5 = R[5];
    float R6 = R[6], R7 = R[7], R8 = R[8];
    float t0 = t[0], t1 = t[1], t2 = t[2];
    float K0 = K[0], K1 = K[1], K2 = K[2];
    float K3 = K[3], K4 = K[4], K5 = K[5];

    for (int i = threadIdx.x; i < N; i += blockDim.x) {
        float vx = verts[3 * i + 0];
        float vy = verts[3 * i + 1];
        float vz = verts[3 * i + 2];
        float p0 = R0 * vx + R1 * vy + R2 * vz + t0;
        float p1 = R3 * vx + R4 * vy + R5 * vz + t1;
        float p2 = R6 * vx + R7 * vy + R8 * vz + t2;
        float zd = p2 + 1e-5f;
        float xn = p0 / zd;
        float yn = p1 / zd;
        float u  = K0 * xn + K1 * yn + K2;
        float vv = K3 * xn + K4 * yn + K5;
        vv = IMGF - vv;
        u  = 2.0f * (u  - IMGF * 0.5f) / IMGF;
        vv = 2.0f * (vv - IMGF * 0.5f) / IMGF;
        v2d[i] = make_float2(u, vv);
    }
    __syncthreads();

    for (int f = threadIdx.x; f < F; f += blockDim.x) {
        int i0 = faces[3 * f + 0];
        int i1 = faces[3 * f + 1];
        int i2 = faces[3 * f + 2];
        float2 v0 = v2d[i0];
        float2 v1 = v2d[i1];
        float2 v2 = v2d[i2];
        float x0 = v0.x, y0 = v0.y;
        float x1 = v1.x, y1 = v1.y;
        float x2 = v2.x, y2 = v2.y;

        float area = (x1 - x0) * (y2 - y0) - (y1 - y0) * (x2 - x0);
        float s = (area > 0.0f) ? 1.0f : ((area < 0.0f) ? -1.0f : 0.0f);

        float dx01 = x1 - x0, dy01 = y1 - y0;
        float A0 = -s * dy01;
        float B0 =  s * dx01;
        float C0 =  s * (dy01 * x0 - dx01 * y0);
        float dx12 = x2 - x1, dy12 = y2 - y1;
        float A1 = -s * dy12;
        float B1 =  s * dx12;
        float C1 =  s * (dy12 * x1 - dx12 * y1);
        float dx20 = x0 - x2, dy20 = y0 - y2;
        float A2 = -s * dy20;
        float B2 =  s * dx20;
        float C2 =  s * (dy20 * x2 - dx20 * y2);

        g_f0[f] = make_float4(A0, B0, C0, A1);
        g_f1[f] = make_float4(B1, C1, A2, B2);
        g_f2[f] = C2;
    }
    if (threadIdx.x == 0) g_ticket = 0;   // redundant with last-block reset; replay-safe
}

// ---------------- Kernel 2: tile-culled rasterize + full reduce ----------------
// 1024 blocks = 32x32 tiles of 8x8 pixels, 64 threads each (one per pixel).
//   pass 1: classify all F faces vs the tile AABB (interval bound on each edge fn)
//   any face fully covering tile -> cov=1 for whole tile, skip pixel loop.
//   else: deterministic ballot+scan compaction of *indices* (u16, 2KB smem),
//         per-pixel loop reads coefficients through L1 (shared across ~7 blocks/SM).
__global__ void __launch_bounds__(TPB) raster_kernel(const float* __restrict__ image_ref,
                                                     int F, float* __restrict__ out) {
    __shared__ unsigned short sidx[FMAX];
    __shared__ unsigned gmask[32];      // 16 chunks x 2 warps
    __shared__ int      goff[32];
    __shared__ float    wsum[2];
    __shared__ int      s_cnt;
    __shared__ int      s_allcov;
    __shared__ int      s_last;

    int tid  = threadIdx.x;
    int lane = tid & 31;
    int wid  = tid >> 5;
    int tx = blockIdx.x & (TILES - 1);
    int ty = blockIdx.x / TILES;
    int col = tx * 8 + (tid & 7);
    int row = ty * 8 + (tid >> 3);
    int pix = row * 256 + col;

    float px =  (2.0f * (float)col + 1.0f - IMGF) * (1.0f / IMGF);
    float py = -((2.0f * (float)row + 1.0f - IMGF) * (1.0f / IMGF));

    // tile center + half extent (pixel centers span +/- 7/256 around center)
    float cx =  (2.0f * (float)(tx * 8) + 8.0f - IMGF) * (1.0f / IMGF);
    float cy = -((2.0f * (float)(ty * 8) + 8.0f - IMGF) * (1.0f / IMGF));
    const float h = 7.0f / 256.0f;

    if (tid == 0) s_allcov = 0;
    __syncthreads();

    // ---- pass 1: classify (16 faces per thread, ballot per 32-face group) ----
    #pragma unroll
    for (int c = 0; c < 16; ++c) {
        int f = c * TPB + tid;
        bool interesting = false;
        if (f < F) {
            float4 a  = g_f0[f];
            float4 b  = g_f1[f];
            float  cc = g_f2[f];
            float w0 = fmaf(a.x, cx, fmaf(a.y, cy, a.z));
            float r0 = (fabsf(a.x) + fabsf(a.y)) * h;
            float w1 = fmaf(a.w, cx, fmaf(b.x, cy, b.y));
            float r1 = (fabsf(a.w) + fabsf(b.x)) * h;
            float w2 = fmaf(b.z, cx, fmaf(b.w, cy, cc));
            float r2 = (fabsf(b.z) + fabsf(b.w)) * h;
            float dmin = fminf(w0 - r0, fminf(w1 - r1, w2 - r2));
            float dmax = fminf(w0 + r0, fminf(w1 + r1, w2 + r2));
            if (dmin * INV_SIGMA > 18.0f) {
                s_allcov = 1;           // face fully covers the tile
            } else if (dmax * INV_SIGMA > -31.0f) {
                interesting = true;     // within soft band or partially covering
            }
        }
        unsigned m = __ballot_sync(0xffffffffu, interesting);
        if (lane == 0) gmask[c * 2 + wid] = m;
    }
    __syncthreads();

    float cov;
    if (s_allcov) {
        cov = 1.0f;                     // whole tile covered: no per-pixel loop
    } else {
        // ---- deterministic exclusive scan of 32 group popcounts (warp 0) ----
        if (tid < 32) {
            int cnt = __popc(gmask[tid]);
            int x = cnt;
            #pragma unroll
            for (int off = 1; off < 32; off <<= 1) {
                int y = __shfl_up_sync(0xffffffffu, x, off);
                if (tid >= off) x += y;
            }
            goff[tid] = x - cnt;
            if (tid == 31) s_cnt = x;
        }
        __syncthreads();

        // ---- index compaction (fixed order: ascending face index) ----
        #pragma unroll
        for (int c = 0; c < 16; ++c) {
            int g = c * 2 + wid;
            unsigned m = gmask[g];
            if (m & (1u << lane)) {
                int f = c * TPB + tid;
                int pos = goff[g] + __popc(m & ((1u << lane) - 1u));
                sidx[pos] = (unsigned short)f;
            }
        }
        __syncthreads();
        int cnt = s_cnt;

        // ---- per-pixel loop over compacted faces (coeffs via L1) ----
        float acc = 0.0f;
        bool covered = false;
        for (int i = 0; i < cnt; ++i) {
            if (!covered) {
                int f = sidx[i];
                float4 a  = g_f0[f];
                float4 b  = g_f1[f];
                float  cc = g_f2[f];
                float w0 = fmaf(a.x, px, fmaf(a.y, py, a.z));
                float w1 = fmaf(a.w, px, fmaf(b.x, py, b.y));
                float w2 = fmaf(b.z, px, fmaf(b.w, py, cc));
                float d  = fminf(w0, fminf(w1, w2));
                float tt = d * INV_SIGMA;
                if (tt > 17.4f) {
                    covered = true;     // sigmoid == 1.0f in fp32 -> cov = 1
                } else if (tt > -30.0f) {
                    float prob = 1.0f / (1.0f + expf(-tt));
                    acc += log1pf(1e-12f - prob);
                }
            }
            if (__all_sync(0xffffffffu, covered)) break;
        }
        cov = covered ? 1.0f : (1.0f - expf(acc));
    }

    // ---- block reduction of squared error (warp shuffle, fixed order) ----
    float df = cov - image_ref[pix];
    float v = df * df;
    #pragma unroll
    for (int off = 16; off > 0; off >>= 1)
        v += __shfl_down_sync(0xffffffffu, v, off);
    if (lane == 0) wsum[wid] = v;
    __syncthreads();
    if (tid == 0) {
        g_partial[blockIdx.x] = wsum[0] + wsum[1];
        __threadfence();
        unsigned tkt = atomicAdd(&g_ticket, 1u);
        s_last = (tkt == gridDim.x - 1) ? 1 : 0;
    }
    __syncthreads();

    // ---- last block performs the deterministic final reduction ----
    if (s_last) {
        __threadfence();
        float s = 0.0f;
        #pragma unroll
        for (int i = 0; i < NBLK / TPB; ++i)
            s += g_partial[i * TPB + tid];      // fixed per-thread order
        #pragma unroll
        for (int off = 16; off > 0; off >>= 1)
            s += __shfl_down_sync(0xffffffffu, s, off);
        if (lane == 0) wsum[wid] = s;
        __syncthreads();
        if (tid == 0) {
            out[0] = wsum[0] + wsum[1];
            g_ticket = 0;               // reset for next graph replay
        }
    }
}

extern "C" void kernel_launch(void* const* d_in, const int* in_sizes, int n_in,
                              void* d_out, int out_size) {
    const float* verts     = (const float*)d_in[0];  // (1,N,3)
    const float* K         = (const float*)d_in[1];  // (1,3,3)
    const float* R         = (const float*)d_in[2];  // (1,3,3)
    const float* t         = (const float*)d_in[3];  // (1,3)
    const float* image_ref = (const float*)d_in[4];  // (256,256)
    const int*   faces     = (const int*)d_in[5];    // (1,F,3)
    float* out = (float*)d_out;

    int N = in_sizes[0] / 3;
    int F = in_sizes[5] / 3;
    if (N > NMAX) N = NMAX;
    if (F > FMAX) F = FMAX;

    prep_kernel<<<1, 1024>>>(verts, K, R, t, faces, N, F);
    raster_kernel<<<NBLK, TPB>>>(image_ref, F, out);
}

// round 10
// speedup vs baseline: 1.4320x; 1.4320x over previous
#include <cuda_runtime.h>
#include <math.h>

#define NMAX 4096
#define FMAX 1024
#define IMGF 256.0f
#define INV_SIGMA (1.0f / 3e-05f)

#define NBLK 256            // 16x16 tiles of 16x16 pixels
#define TPB  256

// Scratch (no allocations allowed in kernel_launch)
__device__ float4 g_f0[FMAX];   // A0,B0,C0,A1
__device__ float4 g_f1[FMAX];   // B1,C1,A2,B2
__device__ float  g_f2[FMAX];   // C2
__device__ float  g_partial[NBLK];
__device__ unsigned g_ticket = 0;

// ---------------- Kernel 1: fully parallel per-face prep ----------------
// Each thread handles ONE face and projects its own 3 vertices (redundant
// projection: ~75 extra FLOPs/face, removes the serial 1-block stage+sync).
__device__ __forceinline__ float2 project_one(const float* __restrict__ verts, int i,
                                              const float* __restrict__ K,
                                              const float* __restrict__ R,
                                              const float* __restrict__ t) {
    float vx = verts[3 * i + 0];
    float vy = verts[3 * i + 1];
    float vz = verts[3 * i + 2];
    float p0 = R[0] * vx + R[1] * vy + R[2] * vz + t[0];
    float p1 = R[3] * vx + R[4] * vy + R[5] * vz + t[1];
    float p2 = R[6] * vx + R[7] * vy + R[8] * vz + t[2];
    float zd = p2 + 1e-5f;
    float xn = p0 / zd;
    float yn = p1 / zd;
    float u  = K[0] * xn + K[1] * yn + K[2];
    float vv = K[3] * xn + K[4] * yn + K[5];
    vv = IMGF - vv;
    u  = 2.0f * (u  - IMGF * 0.5f) / IMGF;
    vv = 2.0f * (vv - IMGF * 0.5f) / IMGF;
    return make_float2(u, vv);
}

__global__ void __launch_bounds__(256) prep_kernel(const float* __restrict__ verts,
                                                   const float* __restrict__ K,
                                                   const float* __restrict__ R,
                                                   const float* __restrict__ t,
                                                   const int* __restrict__ faces,
                                                   int F) {
    int f = blockIdx.x * blockDim.x + threadIdx.x;
    if (f == 0) g_ticket = 0;            // replay-safe (also reset by raster last block)
    if (f >= F) return;

    int i0 = faces[3 * f + 0];
    int i1 = faces[3 * f + 1];
    int i2 = faces[3 * f + 2];
    float2 v0 = project_one(verts, i0, K, R, t);
    float2 v1 = project_one(verts, i1, K, R, t);
    float2 v2 = project_one(verts, i2, K, R, t);
    float x0 = v0.x, y0 = v0.y;
    float x1 = v1.x, y1 = v1.y;
    float x2 = v2.x, y2 = v2.y;

    float area = (x1 - x0) * (y2 - y0) - (y1 - y0) * (x2 - x0);
    float s = (area > 0.0f) ? 1.0f : ((area < 0.0f) ? -1.0f : 0.0f);

    float dx01 = x1 - x0, dy01 = y1 - y0;
    float A0 = -s * dy01;
    float B0 =  s * dx01;
    float C0 =  s * (dy01 * x0 - dx01 * y0);
    float dx12 = x2 - x1, dy12 = y2 - y1;
    float A1 = -s * dy12;
    float B1 =  s * dx12;
    float C1 =  s * (dy12 * x1 - dx12 * y1);
    float dx20 = x0 - x2, dy20 = y0 - y2;
    float A2 = -s * dy20;
    float B2 =  s * dx20;
    float C2 =  s * (dy20 * x2 - dx20 * y2);

    g_f0[f] = make_float4(A0, B0, C0, A1);
    g_f1[f] = make_float4(B1, C1, A2, B2);
    g_f2[f] = C2;
}

// ---------------- Kernel 2: tile-culled rasterize + full reduce ----------------
// 256 blocks = 16x16 tiles of 16x16 pixels, 256 threads (one per pixel).
//   pass 1: classify all F faces vs tile AABB (interval bound per edge fn)
//   any face fully covering tile -> whole tile cov=1, skip pixel loop.
//   else: deterministic ballot+scan compaction of coefficients into smem,
//         per-pixel loop chunked by 8 with ONE __all_sync per chunk.
__global__ void __launch_bounds__(TPB) raster_kernel(const float* __restrict__ image_ref,
                                                     int F, float* __restrict__ out) {
    __shared__ float4   c0[FMAX];
    __shared__ float4   c1[FMAX];
    __shared__ float    c2s[FMAX];
    __shared__ unsigned gmask[32];      // 4 chunks x 8 warps
    __shared__ int      goff[32];
    __shared__ float    wsum[8];
    __shared__ int      s_cnt;
    __shared__ int      s_allcov;
    __shared__ int      s_last;

    int tid  = threadIdx.x;
    int lane = tid & 31;
    int wid  = tid >> 5;
    int tx = blockIdx.x & 15;
    int ty = blockIdx.x >> 4;
    int col = tx * 16 + (tid & 15);
    int row = ty * 16 + (tid >> 4);
    int pix = row * 256 + col;

    float px =  (2.0f * (float)col + 1.0f - IMGF) * (1.0f / IMGF);
    float py = -((2.0f * (float)row + 1.0f - IMGF) * (1.0f / IMGF));

    // tile center + half extent (pixel centers span +/- 15/256 around center)
    float cx =  (2.0f * (float)(tx * 16) + 16.0f - IMGF) * (1.0f / IMGF);
    float cy = -((2.0f * (float)(ty * 16) + 16.0f - IMGF) * (1.0f / IMGF));
    const float h = 15.0f / 256.0f;

    if (tid == 0) s_allcov = 0;
    __syncthreads();

    // ---- pass 1: classify (4 faces/thread, ballot per 32-face group) ----
    #pragma unroll
    for (int c = 0; c < 4; ++c) {
        int f = c * TPB + tid;
        bool interesting = false;
        if (f < F) {
            float4 a  = g_f0[f];
            float4 b  = g_f1[f];
            float  cc = g_f2[f];
            float w0 = fmaf(a.x, cx, fmaf(a.y, cy, a.z));
            float r0 = (fabsf(a.x) + fabsf(a.y)) * h;
            float w1 = fmaf(a.w, cx, fmaf(b.x, cy, b.y));
            float r1 = (fabsf(a.w) + fabsf(b.x)) * h;
            float w2 = fmaf(b.z, cx, fmaf(b.w, cy, cc));
            float r2 = (fabsf(b.z) + fabsf(b.w)) * h;
            float dmin = fminf(w0 - r0, fminf(w1 - r1, w2 - r2));
            float dmax = fminf(w0 + r0, fminf(w1 + r1, w2 + r2));
            if (dmin * INV_SIGMA > 18.0f) {
                s_allcov = 1;           // face fully covers the tile
            } else if (dmax * INV_SIGMA > -31.0f) {
                interesting = true;     // within soft band or partially covering
            }
        }
        unsigned m = __ballot_sync(0xffffffffu, interesting);
        if (lane == 0) gmask[c * 8 + wid] = m;
    }
    __syncthreads();

    float cov;
    if (s_allcov) {
        cov = 1.0f;                     // whole tile covered: no per-pixel loop
    } else {
        // ---- deterministic exclusive scan of 32 group popcounts (warp 0) ----
        if (tid < 32) {
            int cnt = __popc(gmask[tid]);
            int x = cnt;
            #pragma unroll
            for (int off = 1; off < 32; off <<= 1) {
                int y = __shfl_up_sync(0xffffffffu, x, off);
                if (tid >= off) x += y;
            }
            goff[tid] = x - cnt;
            if (tid == 31) s_cnt = x;
        }
        __syncthreads();

        // ---- coefficient compaction (fixed order: ascending face index) ----
        #pragma unroll
        for (int c = 0; c < 4; ++c) {
            int g = c * 8 + wid;
            unsigned m = gmask[g];
            if (m & (1u << lane)) {
                int f = c * TPB + tid;
                int pos = goff[g] + __popc(m & ((1u << lane) - 1u));
                c0[pos]  = g_f0[f];
                c1[pos]  = g_f1[f];
                c2s[pos] = g_f2[f];
            }
        }
        __syncthreads();
        int cnt = s_cnt;

        // ---- per-pixel loop, chunked: one __all_sync per 8 faces ----
        // No per-face "covered" guard: once covered, acc is discarded (cov=1),
        // and log1pf(1e-12 - prob) is always finite, so extra work is harmless.
        float acc = 0.0f;
        bool covered = false;
        int i = 0;
        for (; i + 8 <= cnt; i += 8) {
            #pragma unroll
            for (int j = 0; j < 8; ++j) {
                float4 a  = c0[i + j];
                float4 b  = c1[i + j];
                float  cc = c2s[i + j];
                float w0 = fmaf(a.x, px, fmaf(a.y, py, a.z));
                float w1 = fmaf(a.w, px, fmaf(b.x, py, b.y));
                float w2 = fmaf(b.z, px, fmaf(b.w, py, cc));
                float d  = fminf(w0, fminf(w1, w2));
                float tt = d * INV_SIGMA;
                if (tt > 17.4f) {
                    covered = true;     // sigmoid == 1.0f in fp32 -> cov = 1
                } else if (tt > -30.0f) {
                    float prob = 1.0f / (1.0f + expf(-tt));
                    acc += log1pf(1e-12f - prob);
                }
            }
            if (__all_sync(0xffffffffu, covered)) { i = cnt; break; }
        }
        for (; i < cnt; ++i) {          // remainder (< 8 faces), no sync
            float4 a  = c0[i];
            float4 b  = c1[i];
            float  cc = c2s[i];
            float w0 = fmaf(a.x, px, fmaf(a.y, py, a.z));
            float w1 = fmaf(a.w, px, fmaf(b.x, py, b.y));
            float w2 = fmaf(b.z, px, fmaf(b.w, py, cc));
            float d  = fminf(w0, fminf(w1, w2));
            float tt = d * INV_SIGMA;
            if (tt > 17.4f) {
                covered = true;
            } else if (tt > -30.0f) {
                float prob = 1.0f / (1.0f + expf(-tt));
                acc += log1pf(1e-12f - prob);
            }
        }
        cov = covered ? 1.0f : (1.0f - expf(acc));
    }

    // ---- block reduction of squared error (warp shuffle, fixed order) ----
    float df = cov - image_ref[pix];
    float v = df * df;
    #pragma unroll
    for (int off = 16; off > 0; off >>= 1)
        v += __shfl_down_sync(0xffffffffu, v, off);
    if (lane == 0) wsum[wid] = v;
    __syncthreads();
    if (tid == 0) {
        float bs = 0.0f;
        #pragma unroll
        for (int w = 0; w < 8; ++w) bs += wsum[w];
        g_partial[blockIdx.x] = bs;
        __threadfence();
        unsigned tkt = atomicAdd(&g_ticket, 1u);
        s_last = (tkt == gridDim.x - 1) ? 1 : 0;
    }
    __syncthreads();

    // ---- last block performs the deterministic final reduction ----
    if (s_last) {
        __threadfence();
        float sv = g_partial[tid];      // 256 partials, fixed per-thread mapping
        #pragma unroll
        for (int off = 16; off > 0; off >>= 1)
            sv += __shfl_down_sync(0xffffffffu, sv, off);
        if (lane == 0) wsum[wid] = sv;
        __syncthreads();
        if (tid == 0) {
            float tot = 0.0f;
            #pragma unroll
            for (int w = 0; w < 8; ++w) tot += wsum[w];
            out[0] = tot;
            g_ticket = 0;               // reset for next graph replay
        }
    }
}

extern "C" void kernel_launch(void* const* d_in, const int* in_sizes, int n_in,
                              void* d_out, int out_size) {
    const float* verts     = (const float*)d_in[0];  // (1,N,3)
    const float* K         = (const float*)d_in[1];  // (1,3,3)
    const float* R         = (const float*)d_in[2];  // (1,3,3)
    const float* t         = (const float*)d_in[3];  // (1,3)
    const float* image_ref = (const float*)d_in[4];  // (256,256)
    const int*   faces     = (const int*)d_in[5];    // (1,F,3)
    float* out = (float*)d_out;

    int F = in_sizes[5] / 3;
    if (F > FMAX) F = FMAX;

    prep_kernel<<<(F + 255) / 256, 256>>>(verts, K, R, t, faces, F);
    raster_kernel<<<NBLK, TPB>>>(image_ref, F, out);
}

// round 12
// speedup vs baseline: 1.6617x; 1.1604x over previous
#include <cuda_runtime.h>
#include <math.h>

#define NMAX 4096
#define FMAX 1024
#define IMGF 256.0f
#define INV_SIGMA (1.0f / 3e-05f)

#define NBLK 256            // 16x16 tiles of 16x16 pixels
#define TPB  512            // 2 threads (lane-paired) per pixel

// Scratch (no allocations allowed in kernel_launch)
__device__ float4 g_f0[FMAX];   // A0,B0,C0,A1
__device__ float4 g_f1[FMAX];   // B1,C1,A2,B2
__device__ float  g_f2[FMAX];   // C2
__device__ float  g_partial[NBLK];
__device__ unsigned g_ticket = 0;

// ---------------- Kernel 1: fully parallel per-face prep ----------------
__device__ __forceinline__ float2 project_one(const float* __restrict__ verts, int i,
                                              const float* __restrict__ K,
                                              const float* __restrict__ R,
                                              const float* __restrict__ t) {
    float vx = verts[3 * i + 0];
    float vy = verts[3 * i + 1];
    float vz = verts[3 * i + 2];
    float p0 = R[0] * vx + R[1] * vy + R[2] * vz + t[0];
    float p1 = R[3] * vx + R[4] * vy + R[5] * vz + t[1];
    float p2 = R[6] * vx + R[7] * vy + R[8] * vz + t[2];
    float zd = p2 + 1e-5f;
    float xn = p0 / zd;
    float yn = p1 / zd;
    float u  = K[0] * xn + K[1] * yn + K[2];
    float vv = K[3] * xn + K[4] * yn + K[5];
    vv = IMGF - vv;
    u  = 2.0f * (u  - IMGF * 0.5f) / IMGF;
    vv = 2.0f * (vv - IMGF * 0.5f) / IMGF;
    return make_float2(u, vv);
}

__global__ void __launch_bounds__(256) prep_kernel(const float* __restrict__ verts,
                                                   const float* __restrict__ K,
                                                   const float* __restrict__ R,
                                                   const float* __restrict__ t,
                                                   const int* __restrict__ faces,
                                                   int F) {
    int f = blockIdx.x * blockDim.x + threadIdx.x;
    if (f == 0) g_ticket = 0;            // replay-safe (also reset by raster last block)
    if (f >= F) return;

    int i0 = faces[3 * f + 0];
    int i1 = faces[3 * f + 1];
    int i2 = faces[3 * f + 2];
    float2 v0 = project_one(verts, i0, K, R, t);
    float2 v1 = project_one(verts, i1, K, R, t);
    float2 v2 = project_one(verts, i2, K, R, t);
    float x0 = v0.x, y0 = v0.y;
    float x1 = v1.x, y1 = v1.y;
    float x2 = v2.x, y2 = v2.y;

    float area = (x1 - x0) * (y2 - y0) - (y1 - y0) * (x2 - x0);
    float s = (area > 0.0f) ? 1.0f : ((area < 0.0f) ? -1.0f : 0.0f);

    float dx01 = x1 - x0, dy01 = y1 - y0;
    float A0 = -s * dy01;
    float B0 =  s * dx01;
    float C0 =  s * (dy01 * x0 - dx01 * y0);
    float dx12 = x2 - x1, dy12 = y2 - y1;
    float A1 = -s * dy12;
    float B1 =  s * dx12;
    float C1 =  s * (dy12 * x1 - dx12 * y1);
    float dx20 = x0 - x2, dy20 = y0 - y2;
    float A2 = -s * dy20;
    float B2 =  s * dx20;
    float C2 =  s * (dy20 * x2 - dx20 * y2);

    g_f0[f] = make_float4(A0, B0, C0, A1);
    g_f1[f] = make_float4(B1, C1, A2, B2);
    g_f2[f] = C2;
}

// ---------------- Kernel 2: tile-culled rasterize + full reduce ----------------
// 256 blocks = 16x16 tiles of 16x16 pixels. 512 threads: lanes 2p,2p+1 share
// pixel p, each walking half (even/odd) of the tile's compacted face list.
// Pair combine (covered OR, acc sum) via shfl_xor(1) -> deterministic.
__global__ void __launch_bounds__(TPB) raster_kernel(const float* __restrict__ image_ref,
                                                     int F, float* __restrict__ out) {
    __shared__ float4   c0[FMAX];
    __shared__ float4   c1[FMAX];
    __shared__ float    c2s[FMAX];
    __shared__ unsigned gmask[32];      // 2 chunks x 16 warps
    __shared__ int      goff[32];
    __shared__ float    wsum[16];
    __shared__ int      s_cnt;
    __shared__ int      s_allcov;
    __shared__ int      s_last;

    int tid   = threadIdx.x;
    int lane  = tid & 31;
    int wid   = tid >> 5;
    int p     = tid >> 1;               // pixel index within tile (0..255)
    int slice = tid & 1;                // face-list slice (even/odd)
    int tx = blockIdx.x & 15;
    int ty = blockIdx.x >> 4;
    int col = tx * 16 + (p & 15);
    int row = ty * 16 + (p >> 4);
    int pix = row * 256 + col;

    float px =  (2.0f * (float)col + 1.0f - IMGF) * (1.0f / IMGF);
    float py = -((2.0f * (float)row + 1.0f - IMGF) * (1.0f / IMGF));

    // tile center + half extent (pixel centers span +/- 15/256 around center)
    float cx =  (2.0f * (float)(tx * 16) + 16.0f - IMGF) * (1.0f / IMGF);
    float cy = -((2.0f * (float)(ty * 16) + 16.0f - IMGF) * (1.0f / IMGF));
    const float h = 15.0f / 256.0f;

    if (tid == 0) s_allcov = 0;
    __syncthreads();

    // ---- pass 1: classify (2 faces/thread, ballot per 32-face group) ----
    #pragma unroll
    for (int c = 0; c < 2; ++c) {
        int f = c * TPB + tid;
        bool interesting = false;
        if (f < F) {
            float4 a  = g_f0[f];
            float4 b  = g_f1[f];
            float  cc = g_f2[f];
            float w0 = fmaf(a.x, cx, fmaf(a.y, cy, a.z));
            float r0 = (fabsf(a.x) + fabsf(a.y)) * h;
            float w1 = fmaf(a.w, cx, fmaf(b.x, cy, b.y));
            float r1 = (fabsf(a.w) + fabsf(b.x)) * h;
            float w2 = fmaf(b.z, cx, fmaf(b.w, cy, cc));
            float r2 = (fabsf(b.z) + fabsf(b.w)) * h;
            float dmin = fminf(w0 - r0, fminf(w1 - r1, w2 - r2));
            float dmax = fminf(w0 + r0, fminf(w1 + r1, w2 + r2));
            if (dmin * INV_SIGMA > 18.0f) {
                s_allcov = 1;           // face fully covers the tile
            } else if (dmax * INV_SIGMA > -31.0f) {
                interesting = true;     // within soft band or partially covering
            }
        }
        unsigned m = __ballot_sync(0xffffffffu, interesting);
        if (lane == 0) gmask[c * 16 + wid] = m;
    }
    __syncthreads();

    float cov;
    if (s_allcov) {
        cov = 1.0f;                     // whole tile covered: no per-pixel loop
    } else {
        // ---- deterministic exclusive scan of 32 group popcounts (warp 0) ----
        if (tid < 32) {
            int cnt = __popc(gmask[tid]);
            int x = cnt;
            #pragma unroll
            for (int off = 1; off < 32; off <<= 1) {
                int y = __shfl_up_sync(0xffffffffu, x, off);
                if (tid >= off) x += y;
            }
            goff[tid] = x - cnt;
            if (tid == 31) s_cnt = x;
        }
        __syncthreads();

        // ---- coefficient compaction (fixed order: ascending face index) ----
        #pragma unroll
        for (int c = 0; c < 2; ++c) {
            int g = c * 16 + wid;
            unsigned m = gmask[g];
            if (m & (1u << lane)) {
                int f = c * TPB + tid;
                int pos = goff[g] + __popc(m & ((1u << lane) - 1u));
                c0[pos]  = g_f0[f];
                c1[pos]  = g_f1[f];
                c2s[pos] = g_f2[f];
            }
        }
        __syncthreads();
        int cnt = s_cnt;

        // ---- per-pixel loop: this thread walks indices slice, slice+2, ...
        //      chunked 16 faces (8 per slice) with one pair-combined __all_sync.
        float acc = 0.0f;
        bool covered = false;
        int base = 0;
        for (; base + 16 <= cnt; base += 16) {
            #pragma unroll
            for (int j = 0; j < 8; ++j) {
                int idx = base + slice + 2 * j;
                float4 a  = c0[idx];
                float4 b  = c1[idx];
                float  cc = c2s[idx];
                float w0 = fmaf(a.x, px, fmaf(a.y, py, a.z));
                float w1 = fmaf(a.w, px, fmaf(b.x, py, b.y));
                float w2 = fmaf(b.z, px, fmaf(b.w, py, cc));
                float d  = fminf(w0, fminf(w1, w2));
                float tt = d * INV_SIGMA;
                if (tt > 17.4f) {
                    covered = true;     // sigmoid == 1.0f in fp32 -> cov = 1
                } else if (tt > -30.0f) {
                    float prob = 1.0f / (1.0f + expf(-tt));
                    acc += log1pf(1e-12f - prob);
                }
            }
            // NOTE: shuffle evaluated unconditionally (no short-circuit!) —
            // all 32 lanes must participate in a sync intrinsic.
            bool ocov_chunk = __shfl_xor_sync(0xffffffffu, covered, 1);
            bool paircov = covered || ocov_chunk;
            if (__all_sync(0xffffffffu, paircov)) { base = cnt; break; }
        }
        for (int idx = base + slice; idx < cnt; idx += 2) {   // remainder (no sync)
            float4 a  = c0[idx];
            float4 b  = c1[idx];
            float  cc = c2s[idx];
            float w0 = fmaf(a.x, px, fmaf(a.y, py, a.z));
            float w1 = fmaf(a.w, px, fmaf(b.x, py, b.y));
            float w2 = fmaf(b.z, px, fmaf(b.w, py, cc));
            float d  = fminf(w0, fminf(w1, w2));
            float tt = d * INV_SIGMA;
            if (tt > 17.4f) {
                covered = true;
            } else if (tt > -30.0f) {
                float prob = 1.0f / (1.0f + expf(-tt));
                acc += log1pf(1e-12f - prob);
            }
        }

        // ---- pair combine (unconditional shuffles, fixed order) ----
        bool  ocov = __shfl_xor_sync(0xffffffffu, covered, 1);
        float oacc = __shfl_xor_sync(0xffffffffu, acc, 1);
        covered = covered || ocov;
        float accs = (slice == 0) ? (acc + oacc) : (oacc + acc);  // same pair order
        cov = covered ? 1.0f : (1.0f - expf(accs));
    }

    // ---- block reduction of squared error (even lanes carry pixels) ----
    float v = 0.0f;
    if (slice == 0) {
        float df = cov - image_ref[pix];
        v = df * df;
    }
    #pragma unroll
    for (int off = 16; off > 0; off >>= 1)
        v += __shfl_down_sync(0xffffffffu, v, off);
    if (lane == 0) wsum[wid] = v;
    __syncthreads();
    if (tid == 0) {
        float bs = 0.0f;
        #pragma unroll
        for (int w = 0; w < 16; ++w) bs += wsum[w];
        g_partial[blockIdx.x] = bs;
        __threadfence();
        unsigned tkt = atomicAdd(&g_ticket, 1u);
        s_last = (tkt == gridDim.x - 1) ? 1 : 0;
    }
    __syncthreads();

    // ---- last block performs the deterministic final reduction ----
    if (s_last) {
        __threadfence();
        float sv = (tid < NBLK) ? g_partial[tid] : 0.0f;
        #pragma unroll
        for (int off = 16; off > 0; off >>= 1)
            sv += __shfl_down_sync(0xffffffffu, sv, off);
        if (lane == 0) wsum[wid] = sv;
        __syncthreads();
        if (tid == 0) {
            float tot = 0.0f;
            #pragma unroll
            for (int w = 0; w < 16; ++w) tot += wsum[w];
            out[0] = tot;
            g_ticket = 0;               // reset for next graph replay
        }
    }
}

extern "C" void kernel_launch(void* const* d_in, const int* in_sizes, int n_in,
                              void* d_out, int out_size) {
    const float* verts     = (const float*)d_in[0];  // (1,N,3)
    const float* K         = (const float*)d_in[1];  // (1,3,3)
    const float* R         = (const float*)d_in[2];  // (1,3,3)
    const float* t         = (const float*)d_in[3];  // (1,3)
    const float* image_ref = (const float*)d_in[4];  // (256,256)
    const int*   faces     = (const int*)d_in[5];    // (1,F,3)
    float* out = (float*)d_out;

    int F = in_sizes[5] / 3;
    if (F > FMAX) F = FMAX;

    prep_kernel<<<(F + 255) / 256, 256>>>(verts, K, R, t, faces, F);
    raster_kernel<<<NBLK, TPB>>>(image_ref, F, out);
}